// round 3
// baseline (speedup 1.0000x reference)
#include <cuda_runtime.h>
#include <cuda_bf16.h>
#include <math.h>

// Problem constants (inputs/targets: 8192 x 2048 fp32)
#define NROWS 8192
#define NCOLS 2048
#define LAMB  0.1

#define SORT_BLOCKS 8
#define WIN 1024          // smem window per block

// Scratch: per-row squared error (sorted in place)
__device__ float g_err[NROWS];

// Software grid-barrier state (monotonic across graph replays; wrap-safe)
__device__ unsigned gb_count  = 0;
__device__ unsigned gb_release = 0;

// ---------------------------------------------------------------------------
// Kernel 1: err[row] = sum_d (x[row,d]-t[row,d])^2   (HBM roofline, ~21us)
// ---------------------------------------------------------------------------
__global__ __launch_bounds__(256) void row_sqerr_kernel(
    const float4* __restrict__ x, const float4* __restrict__ t)
{
    const int row = blockIdx.x;
    const float4* xr = x + (size_t)row * (NCOLS / 4);
    const float4* tr = t + (size_t)row * (NCOLS / 4);

    float acc = 0.0f;
    #pragma unroll
    for (int c = threadIdx.x; c < NCOLS / 4; c += 256) {
        float4 a = xr[c];
        float4 b = tr[c];
        float d0 = a.x - b.x;
        float d1 = a.y - b.y;
        float d2 = a.z - b.z;
        float d3 = a.w - b.w;
        acc += d0 * d0 + d1 * d1 + d2 * d2 + d3 * d3;
    }

    #pragma unroll
    for (int off = 16; off > 0; off >>= 1)
        acc += __shfl_down_sync(0xFFFFFFFFu, acc, off);

    __shared__ float warp_sums[8];
    int lane = threadIdx.x & 31;
    int wid  = threadIdx.x >> 5;
    if (lane == 0) warp_sums[wid] = acc;
    __syncthreads();

    if (wid == 0) {
        float v = (lane < 8) ? warp_sums[lane] : 0.0f;
        #pragma unroll
        for (int off = 4; off > 0; off >>= 1)
            v += __shfl_down_sync(0xFFFFFFFFu, v, off);
        if (lane == 0) g_err[row] = v;
    }
}

// ---------------------------------------------------------------------------
// Software grid barrier for SORT_BLOCKS co-resident blocks.
// Arrive: atomic count; every SORT_BLOCKS-th arrival bumps the release gen.
// Wait: spin until release reaches target (wrap-safe signed compare).
// __threadfence() provides release/acquire (gpu-scope fence also invalidates
// L1D on sm_10x); cross-block data additionally uses ldcg/stcg.
// ---------------------------------------------------------------------------
__device__ __forceinline__ void sort_barrier(unsigned target)
{
    __syncthreads();
    if (threadIdx.x == 0) {
        __threadfence();
        unsigned a = atomicAdd(&gb_count, 1u) + 1u;
        if ((a & (SORT_BLOCKS - 1u)) == 0u)
            atomicAdd(&gb_release, 1u);
        while ((int)(atomicAdd(&gb_release, 0u) - target) < 0)
            __nanosleep(32);
        __threadfence();
    }
    __syncthreads();
}

// ---------------------------------------------------------------------------
// Kernel 2 (persistent, 8 blocks x 1024): full bitonic sort of g_err via
// smem windows + in-kernel global stages, then block 0 computes the loss.
// ---------------------------------------------------------------------------
__global__ __launch_bounds__(1024) void sort_finalize_kernel(float* __restrict__ out)
{
    __shared__ float s[WIN];
    __shared__ double s_w1[32], s_w2[32];
    __shared__ double s_bh[32], s_bo[32];
    __shared__ int    s_bk[32];

    const int tid  = threadIdx.x;
    const int bid  = blockIdx.x;
    const int base = bid * WIN;
    const int N    = NROWS;

    // Per-launch release baseline (stable: no block can bump the release
    // before all blocks have read it, since the first barrier needs all 8).
    const unsigned rbase = atomicAdd(&gb_release, 0u);
    unsigned gen = 0;

    // ---- Phase A: local bitonic sort of this block's 1024-window ----
    s[tid] = g_err[base + tid];          // prior kernel's writes: safe plain load
    __syncthreads();

    for (int k = 2; k <= 1024; k <<= 1) {
        for (int j = k >> 1; j > 0; j >>= 1) {
            if (tid < 512) {
                int r = tid & (j - 1);
                int i = ((tid - r) << 1) | r;
                int gi = base + i;
                bool up = ((gi & k) == 0);
                float a = s[i];
                float b = s[i + j];
                if (up ? (a > b) : (a < b)) { s[i] = b; s[i + j] = a; }
            }
            __syncthreads();
        }
    }
    __stcg(&g_err[base + tid], s[tid]);
    sort_barrier(rbase + ++gen);

    const int gt = base + tid;           // global element/thread id [0, 8192)

    // ---- Merge stages k = 2048, 4096, 8192 ----
    for (int k = 2048; k <= 8192; k <<= 1) {
        // global sub-stages (pairs span >= 1024 -> cross windows)
        for (int j = k >> 1; j >= 1024; j >>= 1) {
            if (gt < NROWS / 2) {
                int r = gt & (j - 1);
                int i = ((gt - r) << 1) | r;
                bool up = ((i & k) == 0);
                float a = __ldcg(&g_err[i]);
                float b = __ldcg(&g_err[i + j]);
                if (up ? (a > b) : (a < b)) {
                    __stcg(&g_err[i], b);
                    __stcg(&g_err[i + j], a);
                }
            }
            sort_barrier(rbase + ++gen);
        }
        // windowed sub-stages j = 512..1 (direction constant per window)
        s[tid] = __ldcg(&g_err[base + tid]);
        __syncthreads();
        const bool up = ((base & k) == 0);
        for (int j = 512; j > 0; j >>= 1) {
            if (tid < 512) {
                int r = tid & (j - 1);
                int i = ((tid - r) << 1) | r;
                float a = s[i];
                float b = s[i + j];
                if (up ? (a > b) : (a < b)) { s[i] = b; s[i + j] = a; }
            }
            __syncthreads();
        }
        __stcg(&g_err[base + tid], s[tid]);
        sort_barrier(rbase + ++gen);
    }

    if (bid != 0) return;

    // ---- Finalize (block 0): fp64 shfl scan of (sum, sumsq), h(k) argmin ----
    const int lane = tid & 31;
    const int wid  = tid >> 5;

    float ev[8];
    double l1 = 0.0, l2 = 0.0;
    #pragma unroll
    for (int i = 0; i < 8; i++) {
        ev[i] = __ldcg(&g_err[tid * 8 + i]);
        double d = (double)ev[i];
        l1 += d;
        l2 += d * d;
    }

    // warp inclusive scan
    double i1 = l1, i2 = l2;
    #pragma unroll
    for (int off = 1; off < 32; off <<= 1) {
        double a = __shfl_up_sync(0xFFFFFFFFu, i1, off);
        double b = __shfl_up_sync(0xFFFFFFFFu, i2, off);
        if (lane >= off) { i1 += a; i2 += b; }
    }
    if (lane == 31) { s_w1[wid] = i1; s_w2[wid] = i2; }
    __syncthreads();

    if (wid == 0) {
        double a1 = s_w1[lane], a2 = s_w2[lane];
        #pragma unroll
        for (int off = 1; off < 32; off <<= 1) {
            double x = __shfl_up_sync(0xFFFFFFFFu, a1, off);
            double y = __shfl_up_sync(0xFFFFFFFFu, a2, off);
            if (lane >= off) { a1 += x; a2 += y; }
        }
        s_w1[lane] = a1;
        s_w2[lane] = a2;
    }
    __syncthreads();

    double base1 = (wid == 0) ? 0.0 : s_w1[wid - 1];
    double base2 = (wid == 0) ? 0.0 : s_w2[wid - 1];
    double tot1 = s_w1[31];
    double tot2 = s_w2[31];
    double ex1 = base1 + i1 - l1;    // exclusive prefix of this thread's chunk
    double ex2 = base2 + i2 - l2;

    const double total_scatter = tot2 - tot1 * tot1 / (double)N;

    double bestH = INFINITY, bestObj = 0.0;
    int bestK = 0x7FFFFFFF;
    double p1 = ex1, p2 = ex2;
    #pragma unroll
    for (int i = 0; i < 8; i++) {
        double d = (double)ev[i];
        p1 += d;
        p2 += d * d;
        int k = tid * 8 + i + 1;
        if (k <= N - 1) {
            double cin  = (double)k;
            double cout = (double)(N - k);
            double r1   = tot1 - p1;
            double win  = (p2 - p1 * p1 / cin) + ((tot2 - p2) - r1 * r1 / cout);
            double h    = win / total_scatter;
            if (h < bestH) { bestH = h; bestK = k; bestObj = p1 / cin; }
        }
    }

    #pragma unroll
    for (int off = 16; off > 0; off >>= 1) {
        double h2 = __shfl_down_sync(0xFFFFFFFFu, bestH, off);
        int    k2 = __shfl_down_sync(0xFFFFFFFFu, bestK, off);
        double o2 = __shfl_down_sync(0xFFFFFFFFu, bestObj, off);
        if (h2 < bestH || (h2 == bestH && k2 < bestK)) {
            bestH = h2; bestK = k2; bestObj = o2;
        }
    }
    if (lane == 0) { s_bh[wid] = bestH; s_bk[wid] = bestK; s_bo[wid] = bestObj; }
    __syncthreads();

    if (wid == 0) {
        double h = s_bh[lane];
        int    k = s_bk[lane];
        double o = s_bo[lane];
        #pragma unroll
        for (int off = 16; off > 0; off >>= 1) {
            double h2 = __shfl_down_sync(0xFFFFFFFFu, h, off);
            int    k2 = __shfl_down_sync(0xFFFFFFFFu, k, off);
            double o2 = __shfl_down_sync(0xFFFFFFFFu, o, off);
            if (h2 < h || (h2 == h && k2 < k)) { h = h2; k = k2; o = o2; }
        }
        if (lane == 0) out[0] = (float)(o + LAMB * h);
    }
}

// ---------------------------------------------------------------------------
extern "C" void kernel_launch(void* const* d_in, const int* in_sizes, int n_in,
                              void* d_out, int out_size)
{
    const float4* x = (const float4*)d_in[0];
    const float4* t = (const float4*)d_in[1];
    float* out = (float*)d_out;

    row_sqerr_kernel<<<NROWS, 256>>>(x, t);
    sort_finalize_kernel<<<SORT_BLOCKS, 1024>>>(out);
}

// round 4
// speedup vs baseline: 1.5007x; 1.5007x over previous
#include <cuda_runtime.h>
#include <cuda_bf16.h>
#include <math.h>

// Problem constants (inputs/targets: 8192 x 2048 fp32)
#define NROWS 8192
#define NCOLS 2048
#define LAMB  0.1

// Scratch: per-row squared error (sorted in place)
__device__ float g_err[NROWS];

// ---------------------------------------------------------------------------
// Kernel 1: err[row] = sum_d (x[row,d]-t[row,d])^2   (HBM roofline, ~21us)
// ---------------------------------------------------------------------------
__global__ __launch_bounds__(256) void row_sqerr_kernel(
    const float4* __restrict__ x, const float4* __restrict__ t)
{
    const int row = blockIdx.x;
    const float4* xr = x + (size_t)row * (NCOLS / 4);
    const float4* tr = t + (size_t)row * (NCOLS / 4);

    float acc = 0.0f;
    #pragma unroll
    for (int c = threadIdx.x; c < NCOLS / 4; c += 256) {
        float4 a = xr[c];
        float4 b = tr[c];
        float d0 = a.x - b.x;
        float d1 = a.y - b.y;
        float d2 = a.z - b.z;
        float d3 = a.w - b.w;
        acc += d0 * d0 + d1 * d1 + d2 * d2 + d3 * d3;
    }

    #pragma unroll
    for (int off = 16; off > 0; off >>= 1)
        acc += __shfl_down_sync(0xFFFFFFFFu, acc, off);

    __shared__ float warp_sums[8];
    int lane = threadIdx.x & 31;
    int wid  = threadIdx.x >> 5;
    if (lane == 0) warp_sums[wid] = acc;
    __syncthreads();

    if (wid == 0) {
        float v = (lane < 8) ? warp_sums[lane] : 0.0f;
        #pragma unroll
        for (int off = 4; off > 0; off >>= 1)
            v += __shfl_down_sync(0xFFFFFFFFu, v, off);
        if (lane == 0) g_err[row] = v;
    }
}

// ---------------------------------------------------------------------------
// Bitonic helpers. Stage (k,j): pair (i, i^j); element at the LOWER index
// keeps min iff ascending (up), where up = ((i & k) == 0).
// ---------------------------------------------------------------------------
__device__ __forceinline__ void cmpswap(float& a, float& b, bool up)
{
    float lo = fminf(a, b);
    float hi = fmaxf(a, b);
    a = up ? lo : hi;
    b = up ? hi : lo;
}

// ---------------------------------------------------------------------------
// Kernel A: 4 blocks x 1024 threads; each block fully sorts its 2048-window
// (stages k=2..2048, direction from GLOBAL index). 2 elems/thread in regs:
// j>=64 via smem exchange, j=2..32 via shfl_xor, j=1 in registers.
// ---------------------------------------------------------------------------
__global__ __launch_bounds__(1024) void sort_local_2048()
{
    __shared__ float s[2048];
    const int t    = threadIdx.x;
    const int base = blockIdx.x * 2048;
    const int li   = 2 * t;          // local index of first owned element
    const int gi   = base + li;      // global index (for direction)

    float2 v2 = reinterpret_cast<const float2*>(g_err)[(base >> 1) + t];
    float v0 = v2.x, v1 = v2.y;

    for (int k = 2; k <= 2048; k <<= 1) {
        const bool up = ((gi & k) == 0);

        // smem sub-stages: j = k/2 .. 64
        for (int j = k >> 1; j >= 64; j >>= 1) {
            s[li]     = v0;
            s[li + 1] = v1;
            __syncthreads();
            int pb = li ^ j;                 // partner base (j >= 2)
            float p0 = s[pb];
            float p1 = s[pb + 1];
            bool keep_min = (up == ((li & j) == 0));
            v0 = keep_min ? fminf(v0, p0) : fmaxf(v0, p0);
            v1 = keep_min ? fminf(v1, p1) : fmaxf(v1, p1);
            __syncthreads();
        }

        // shfl sub-stages: j = min(k/2, 32) .. 2  (lane offset d = j/2 <= 16)
        int jstart = (k >> 1) < 32 ? (k >> 1) : 32;
        for (int j = jstart; j >= 2; j >>= 1) {
            int d = j >> 1;
            float p0 = __shfl_xor_sync(0xFFFFFFFFu, v0, d);
            float p1 = __shfl_xor_sync(0xFFFFFFFFu, v1, d);
            bool keep_min = (up == ((t & d) == 0));
            v0 = keep_min ? fminf(v0, p0) : fmaxf(v0, p0);
            v1 = keep_min ? fminf(v1, p1) : fmaxf(v1, p1);
        }

        // j = 1: intra-thread
        cmpswap(v0, v1, up);
    }

    reinterpret_cast<float2*>(g_err)[(base >> 1) + t] = make_float2(v0, v1);
}

// ---------------------------------------------------------------------------
// Kernel C: single block, 1024 threads, 8 elems/thread in registers.
// Runs stages k=4096 and k=8192 (all their sub-stages fit in one block):
// j>=256 via smem, j=8..128 via shfl_xor, j<=4 in registers.
// Afterwards each thread holds 8 CONSECUTIVE sorted elements -> finalize
// (fp64 scan of (sum,sumsq), h(k) argmin) runs fused, in-register.
// ---------------------------------------------------------------------------
__global__ __launch_bounds__(1024) void merge_finalize_kernel(float* __restrict__ out)
{
    __shared__ float  s[8192];       // 32 KB
    __shared__ double s_w1[32], s_w2[32];
    __shared__ float  s_bh[32];
    __shared__ int    s_bk[32];
    __shared__ double s_bp[32];

    const int t  = threadIdx.x;
    const int li = 8 * t;
    const int N  = NROWS;

    float v[8];
    {
        float4 a = reinterpret_cast<const float4*>(g_err)[2 * t];
        float4 b = reinterpret_cast<const float4*>(g_err)[2 * t + 1];
        v[0] = a.x; v[1] = a.y; v[2] = a.z; v[3] = a.w;
        v[4] = b.x; v[5] = b.y; v[6] = b.z; v[7] = b.w;
    }

    for (int k = 4096; k <= 8192; k <<= 1) {
        const bool up = ((li & k) == 0);

        // smem sub-stages: j = k/2 .. 256
        for (int j = k >> 1; j >= 256; j >>= 1) {
            reinterpret_cast<float4*>(s)[2 * t]     = make_float4(v[0], v[1], v[2], v[3]);
            reinterpret_cast<float4*>(s)[2 * t + 1] = make_float4(v[4], v[5], v[6], v[7]);
            __syncthreads();
            int pb = li ^ j;                 // partner block of 8 (j multiple of 256)
            float4 p0 = reinterpret_cast<const float4*>(s)[pb >> 2];
            float4 p1 = reinterpret_cast<const float4*>(s)[(pb >> 2) + 1];
            float p[8] = {p0.x, p0.y, p0.z, p0.w, p1.x, p1.y, p1.z, p1.w};
            bool keep_min = (up == ((li & j) == 0));
            #pragma unroll
            for (int e = 0; e < 8; e++)
                v[e] = keep_min ? fminf(v[e], p[e]) : fmaxf(v[e], p[e]);
            __syncthreads();
        }

        // shfl sub-stages: j = 128 .. 8 (lane offset d = j/8 = 16..1)
        #pragma unroll
        for (int j = 128; j >= 8; j >>= 1) {
            int d = j >> 3;
            bool keep_min = (up == ((t & d) == 0));
            #pragma unroll
            for (int e = 0; e < 8; e++) {
                float p = __shfl_xor_sync(0xFFFFFFFFu, v[e], d);
                v[e] = keep_min ? fminf(v[e], p) : fmaxf(v[e], p);
            }
        }

        // intra-thread sub-stages: j = 4, 2, 1
        #pragma unroll
        for (int j = 4; j >= 1; j >>= 1)
            #pragma unroll
            for (int e = 0; e < 8; e++)
                if ((e & j) == 0)
                    cmpswap(v[e], v[e | j], up);
    }

    // ---- Finalize: v[0..7] = sorted elements [8t, 8t+8) ascending ----
    const int lane = t & 31;
    const int wid  = t >> 5;

    double l1 = 0.0, l2 = 0.0;
    #pragma unroll
    for (int i = 0; i < 8; i++) {
        double d = (double)v[i];
        l1 += d;
        l2 += d * d;
    }

    // warp inclusive scan of (l1, l2)
    double i1 = l1, i2 = l2;
    #pragma unroll
    for (int off = 1; off < 32; off <<= 1) {
        double a = __shfl_up_sync(0xFFFFFFFFu, i1, off);
        double b = __shfl_up_sync(0xFFFFFFFFu, i2, off);
        if (lane >= off) { i1 += a; i2 += b; }
    }
    if (lane == 31) { s_w1[wid] = i1; s_w2[wid] = i2; }
    __syncthreads();

    if (wid == 0) {
        double a1 = s_w1[lane], a2 = s_w2[lane];
        #pragma unroll
        for (int off = 1; off < 32; off <<= 1) {
            double x = __shfl_up_sync(0xFFFFFFFFu, a1, off);
            double y = __shfl_up_sync(0xFFFFFFFFu, a2, off);
            if (lane >= off) { a1 += x; a2 += y; }
        }
        s_w1[lane] = a1;
        s_w2[lane] = a2;
    }
    __syncthreads();

    double base1 = (wid == 0) ? 0.0 : s_w1[wid - 1];
    double base2 = (wid == 0) ? 0.0 : s_w2[wid - 1];
    double tot1 = s_w1[31];
    double tot2 = s_w2[31];
    double p1 = base1 + i1 - l1;     // exclusive prefix of this thread's chunk
    double p2 = base2 + i2 - l2;

    const double ts = tot2 - tot1 * tot1 / (double)N;
    const float invTS = (float)(1.0 / ts);

    // h(k) candidates: fp64 for the cancelling numerators, fp32 for divides.
    float  bestH = INFINITY;
    int    bestK = 0x7FFFFFFF;
    double bestP1 = 0.0;
    #pragma unroll
    for (int i = 0; i < 8; i++) {
        double d = (double)v[i];
        p1 += d;
        p2 += d * d;
        int k = t * 8 + i + 1;
        if (k <= N - 1) {
            double cin  = (double)k;
            double cout = (double)(N - k);
            double r1   = tot1 - p1;
            double num_in  = p2 * cin - p1 * p1;            // = within_in  * cin
            double num_out = (tot2 - p2) * cout - r1 * r1;  // = within_out * cout
            float h = ((float)num_in  / (float)cin +
                       (float)num_out / (float)cout) * invTS;
            if (h < bestH) { bestH = h; bestK = k; bestP1 = p1; }
        }
    }

    // warp argmin (h, then k for first-index tiebreak)
    #pragma unroll
    for (int off = 16; off > 0; off >>= 1) {
        float  h2 = __shfl_down_sync(0xFFFFFFFFu, bestH, off);
        int    k2 = __shfl_down_sync(0xFFFFFFFFu, bestK, off);
        double q2 = __shfl_down_sync(0xFFFFFFFFu, bestP1, off);
        if (h2 < bestH || (h2 == bestH && k2 < bestK)) {
            bestH = h2; bestK = k2; bestP1 = q2;
        }
    }
    if (lane == 0) { s_bh[wid] = bestH; s_bk[wid] = bestK; s_bp[wid] = bestP1; }
    __syncthreads();

    if (wid == 0) {
        float  h = s_bh[lane];
        int    k = s_bk[lane];
        double q = s_bp[lane];
        #pragma unroll
        for (int off = 16; off > 0; off >>= 1) {
            float  h2 = __shfl_down_sync(0xFFFFFFFFu, h, off);
            int    k2 = __shfl_down_sync(0xFFFFFFFFu, k, off);
            double q2 = __shfl_down_sync(0xFFFFFFFFu, q, off);
            if (h2 < h || (h2 == h && k2 < k)) { h = h2; k = k2; q = q2; }
        }
        if (lane == 0) {
            double obj = q / (double)k;
            out[0] = (float)(obj + LAMB * (double)h);
        }
    }
}

// ---------------------------------------------------------------------------
extern "C" void kernel_launch(void* const* d_in, const int* in_sizes, int n_in,
                              void* d_out, int out_size)
{
    const float4* x = (const float4*)d_in[0];
    const float4* t = (const float4*)d_in[1];
    float* out = (float*)d_out;

    row_sqerr_kernel<<<NROWS, 256>>>(x, t);
    sort_local_2048<<<4, 1024>>>();
    merge_finalize_kernel<<<1, 1024>>>(out);
}